// round 15
// baseline (speedup 1.0000x reference)
#include <cuda_runtime.h>
#include <cuda_fp16.h>
#include <math.h>
#include <stdint.h>

// ---------------- problem constants ----------------
#define Nn    4096
#define Bb    32
#define Cc    16
#define Hh    64
#define Kc    3
#define P0    80
#define P1    128
#define NC0   (Bb*P0)     // 2560
#define NC1   (Bb*P1)     // 4096
#define KP0   (Kc*P0)     // 240
#define KP1   (Kc*P1)     // 384
#define GH    256
#define ROWS  (Bb*Nn)     // 131072

// ---------------- GEMM tiling (fp16 operands, fp32 accum) ----------------
#define BM   128
#define BN   256
#define BSTG 16384                 // 32x256 fp16 packed B (one k32 stage)
#define SMEM_MAIN 66560            // max(4*BSTG=65536, epilogue 64*260*4=66560)

// ---------------- scratch (__device__ globals, fragment-packed fp16) -------
// A for supp GEMM: [z(3)][mt(32)][kb16(256)][g16(8)][lane(32)] uint4
__device__ uint4 g_GPh   [(size_t)Kc * 32 * 256 * 8 * 32];     // 100.7 MB
// B (comb): [nt(<=16)][kb16(256)][jq(16)][lane(32)] uint4
__device__ uint4 g_combPh[(size_t)16 * 256 * 16 * 32];         // 33.5 MB
// A for gates GEMM: [mt(1024)][kb16(<=24)][g16(8)][lane(32)] uint4
__device__ uint4 g_suppPh[(size_t)1024 * 24 * 8 * 32];         // 100.7 MB
// B (W): [kb16(<=24)][jq(16)][lane(32)] uint4
__device__ uint4 g_WtPh  [(size_t)24 * 16 * 32];
__device__ float g_ht0   [(size_t)ROWS * Hh];                  // 33.5 MB

// ---------------- helpers ----------------
__device__ __forceinline__ float sigm(float x) { return 1.f / (1.f + expf(-x)); }

__device__ __forceinline__ uint32_t h2pack(float a, float b) {
    __half2 h = __halves2half2(__float2half_rn(a), __float2half_rn(b));
    return *reinterpret_cast<uint32_t*>(&h);
}

__device__ __forceinline__ void cp16(void* s, const void* g) {
    uint32_t a;
    asm("{ .reg .u64 t; cvta.to.shared.u64 t, %1; cvt.u32.u64 %0, t; }" : "=r"(a) : "l"(s));
    asm volatile("cp.async.cg.shared.global [%0], [%1], 16;" :: "r"(a), "l"(g));
}
#define CP_COMMIT() asm volatile("cp.async.commit_group;")
#define CP_WAIT2()  asm volatile("cp.async.wait_group 2;")
#define CP_WAIT0()  asm volatile("cp.async.wait_group 0;")

// fp16 MMA: D(f32) += A(f16) * B(f16); m16n8k16
#define MMAH(accq, af, b0, b1) \
    asm volatile("mma.sync.aligned.m16n8k16.row.col.f32.f16.f16.f32 " \
        "{%0,%1,%2,%3}, {%4,%5,%6,%7}, {%8,%9}, {%0,%1,%2,%3};" \
        : "+f"((accq)[0]), "+f"((accq)[1]), "+f"((accq)[2]), "+f"((accq)[3]) \
        : "r"((af).x), "r"((af).y), "r"((af).z), "r"((af).w), "r"(b0), "r"(b1))

// ---------------------------------------------------------------------------
// Packed-fragment fp16 GEMM, software-pipelined, A DIRECT FROM GMEM.
// C[128x256] per CTA; K in 32-wide tiles. 8 warps (2x4), warp tile 64x64.
// A fragments LDG.128'd straight into registers (depth-1 prefetch, L2-hit);
// only B flows through smem (4-stage cp.async ring, 16KB/stage).
// Register ping-pong on B fragments hides LDS latency under MMA blocks.
// MODE 0: emit supp as packed fp16 A-fragments for the gates GEMM.
// MODE 1: fused bias + LSTM.
// nkt in 32-K tiles (always even here); nktOut (MODE 0) in 16-K blocks.
// ---------------------------------------------------------------------------
template<int MODE, int PC>
__global__ void __launch_bounds__(256, 1)
gemm_fp16(const uint4* __restrict__ Ap, const uint4* __restrict__ Bp,
          int nkt, uint4* __restrict__ outP, int nktOut,
          const float* __restrict__ bias, const float* __restrict__ cpre,
          float* __restrict__ ho1, float* __restrict__ ho2,
          float* __restrict__ co,  float* __restrict__ hscr)
{
    extern __shared__ char smem[];
    const int tid  = threadIdx.x;
    const int wid  = tid >> 5, lane = tid & 31;
    const int wm   = wid >> 2, wn = wid & 3;
    const int bm0  = blockIdx.y * BM;
    const int bn0  = blockIdx.x * BN;
    const int zz   = blockIdx.z;

    // uint4 units: A kb16 block = 256, B kb16 block = 512 (k32 tile: 512 / 1024)
    const uint4* Abase = Ap + ((size_t)zz * gridDim.y + blockIdx.y) * (size_t)(2 * nkt) * 256;
    const uint4* Bbase = Bp + (size_t)blockIdx.x * (size_t)(2 * nkt) * 512;
    // this warp's A-fragment lane pointer: element (k2, mi) at [k2*256 + mi*32]
    const uint4* Aw = Abase + (size_t)(wm * 4) * 32 + lane;

    float acc[4][8][4];
    #pragma unroll
    for (int ai = 0; ai < 4; ai++)
        #pragma unroll
        for (int bj = 0; bj < 8; bj++)
            #pragma unroll
            for (int cq = 0; cq < 4; cq++) acc[ai][bj][cq] = 0.f;

    auto pf = [&](int sg, int kt) {
        char* sB = smem + sg * BSTG;
        const uint4* bg = Bbase + (size_t)kt * 1024;
        #pragma unroll
        for (int i = 0; i < 4; i++)
            cp16(sB + (tid + i * 256) * 16, bg + tid + i * 256);
    };

    pf(0, 0); CP_COMMIT();
    if (nkt > 1) pf(1, 1);
    CP_COMMIT();
    if (nkt > 2) pf(2, 2);
    CP_COMMIT();

    // A fragments for tile 0 (direct LDG, coalesced 512B/request)
    uint4 aCur[8], aNext[8];
    #pragma unroll
    for (int q = 0; q < 8; q++)
        aCur[q] = Aw[(q >> 2) * 256 + (q & 3) * 32];

    CP_WAIT2();
    __syncthreads();

    uint4 bf0[4], bf1[4];
    {   // B k2=0 frags of tile 0
        const uint4* sB = (const uint4*)(smem);
        #pragma unroll
        for (int jq = 0; jq < 4; jq++) bf0[jq] = sB[(wn * 4 + jq) * 32 + lane];
    }

    for (int kt = 0; kt < nkt; kt++) {
        const int sg = kt & 3;
        const uint4* sB = (const uint4*)(smem + sg * BSTG);

        // prefetch next tile's A into registers (hidden under both MMA blocks)
        if (kt + 1 < nkt) {
            const uint4* An = Aw + (size_t)(kt + 1) * 512;
            #pragma unroll
            for (int q = 0; q < 8; q++)
                aNext[q] = An[(q >> 2) * 256 + (q & 3) * 32];
        }

        // load B k2=1 frags (hidden under the k2=0 MMA block below)
        #pragma unroll
        for (int jq = 0; jq < 4; jq++) bf1[jq] = sB[512 + (wn * 4 + jq) * 32 + lane];

        // MMAs for k2=0 (aCur[0..3])
        #pragma unroll
        for (int mi = 0; mi < 4; mi++)
            #pragma unroll
            for (int jq = 0; jq < 4; jq++) {
                MMAH(acc[mi][jq * 2],     aCur[mi], bf0[jq].x, bf0[jq].y);
                MMAH(acc[mi][jq * 2 + 1], aCur[mi], bf0[jq].z, bf0[jq].w);
            }

        if (kt + 3 < nkt) pf((kt + 3) & 3, kt + 3);
        CP_COMMIT();

        if (kt + 1 < nkt) {
            CP_WAIT2();
            __syncthreads();
            const uint4* sB2 = (const uint4*)(smem + ((kt + 1) & 3) * BSTG);
            // next tile's B k2=0 frags (hidden under the k2=1 MMA block)
            #pragma unroll
            for (int jq = 0; jq < 4; jq++) bf0[jq] = sB2[(wn * 4 + jq) * 32 + lane];
        }

        // MMAs for k2=1 (aCur[4..7])
        #pragma unroll
        for (int mi = 0; mi < 4; mi++)
            #pragma unroll
            for (int jq = 0; jq < 4; jq++) {
                MMAH(acc[mi][jq * 2],     aCur[4 + mi], bf1[jq].x, bf1[jq].y);
                MMAH(acc[mi][jq * 2 + 1], aCur[4 + mi], bf1[jq].z, bf1[jq].w);
            }

        #pragma unroll
        for (int q = 0; q < 8; q++) aCur[q] = aNext[q];
    }
    CP_WAIT0();
    __syncthreads();

    // ---------------- epilogue (staged per 64-row half) ----------------
    const int lq = lane >> 2, lr = lane & 3;
    float* sC = (float*)smem;                 // [64][260] = 66560 B

    for (int h = 0; h < 2; h++) {
        if (wm == h) {
            #pragma unroll
            for (int mi = 0; mi < 4; mi++)
                #pragma unroll
                for (int j = 0; j < 8; j++) {
                    const int r0 = mi * 16 + lq;
                    const int c0 = wn * 64 + j * 8 + lr * 2;
                    sC[r0 * 260 + c0]           = acc[mi][j][0];
                    sC[r0 * 260 + c0 + 1]       = acc[mi][j][1];
                    sC[(r0 + 8) * 260 + c0]     = acc[mi][j][2];
                    sC[(r0 + 8) * 260 + c0 + 1] = acc[mi][j][3];
                }
        }
        __syncthreads();

        if constexpr (MODE == 0) {
            // emit packed fp16 A-fragments for the gates GEMM
            // 2048 uint4 per half: [lkb(16)][g16h(4)][lane(32)]
            #pragma unroll 4
            for (int it = 0; it < 8; it++) {
                const int idx  = it * 256 + tid;       // 0..2047
                const int ln2  = idx & 31;
                const int g16h = (idx >> 5) & 3;
                const int lkb  = idx >> 7;             // 0..15
                const int gg = ln2 >> 2, tt = ln2 & 3;
                const int rl0 = g16h * 16 + gg;        // local row in half
                const int c0  = lkb * 16 + tt * 2;
                uint4 ha;
                ha.x = h2pack(sC[rl0 * 260 + c0],           sC[rl0 * 260 + c0 + 1]);
                ha.y = h2pack(sC[(rl0 + 8) * 260 + c0],     sC[(rl0 + 8) * 260 + c0 + 1]);
                ha.z = h2pack(sC[rl0 * 260 + c0 + 8],       sC[rl0 * 260 + c0 + 9]);
                ha.w = h2pack(sC[(rl0 + 8) * 260 + c0 + 8], sC[(rl0 + 8) * 260 + c0 + 9]);
                const int gcb  = bn0 + lkb * 16;       // 16-aligned col block
                const int bi   = gcb / PC;
                const int kidx = zz * PC + (gcb - bi * PC);
                const int kt2  = kidx >> 4;
                const int mtg  = bi * (Nn / 128) + (bm0 >> 7);
                const int g16g = h * 4 + g16h;
                const size_t f4i =
                    (((size_t)mtg * nktOut + kt2) * 8 + g16g) * 32 + ln2;
                outP[f4i] = ha;
            }
        } else {
            // fused bias + LSTM; cols 0..63=i, 64..127=f, 128..191=o, 192..255=g
            #pragma unroll 4
            for (int it = 0; it < 16; it++) {
                const int idx  = it * 256 + tid;       // 0..4095
                const int row  = idx >> 6;             // 0..63
                const int hc   = idx & 63;
                const float gi = sC[row * 260 + hc]        + __ldg(bias + hc);
                const float gf = sC[row * 260 + 64 + hc]   + __ldg(bias + 64 + hc);
                const float go = sC[row * 260 + 128 + hc]  + __ldg(bias + 128 + hc);
                const float gg = sC[row * 260 + 192 + hc]  + __ldg(bias + 192 + hc);
                const size_t m  = (size_t)bm0 + h * 64 + row;
                const size_t ix = m * Hh + hc;
                const float ct = sigm(gf) * cpre[ix] + sigm(gi) * tanhf(gg);
                const float ht = sigm(go) * tanhf(ct);
                ho1[ix] = ht;
                if (ho2)  ho2[ix]  = ht;
                co[ix] = ct;
                if (hscr) hscr[ix] = ht;
            }
        }
        __syncthreads();
    }
}

// ---------------------------------------------------------------------------
// pack kernels (fp16 fragments, round-to-nearest)
// ---------------------------------------------------------------------------
__global__ void packG_k(const float* __restrict__ G)
{
    const int idx = blockIdx.x * blockDim.x + threadIdx.x;
    if (idx >= Kc * 32 * 256 * 8 * 32) return;
    const int lane = idx & 31;
    const int g16  = (idx >> 5) & 7;
    const int kb   = (idx >> 8) & 255;
    const int mt   = (idx >> 16) & 31;
    const int zi   = idx >> 21;
    const int gg = lane >> 2, tt = lane & 3;
    const int r = mt * 128 + g16 * 16 + gg;
    const int c = kb * 16 + tt * 2;
    const float* Gz = G + (size_t)zi * Nn * Nn;
    uint4 v;
    v.x = h2pack(Gz[(size_t)r * Nn + c],           Gz[(size_t)r * Nn + c + 1]);
    v.y = h2pack(Gz[(size_t)(r + 8) * Nn + c],     Gz[(size_t)(r + 8) * Nn + c + 1]);
    v.z = h2pack(Gz[(size_t)r * Nn + c + 8],       Gz[(size_t)r * Nn + c + 9]);
    v.w = h2pack(Gz[(size_t)(r + 8) * Nn + c + 8], Gz[(size_t)(r + 8) * Nn + c + 9]);
    g_GPh[idx] = v;
}

__device__ __forceinline__ float comb0_val(const float* x, const float* h0, int m, int col) {
    const int b = col / P0, p = col - b * P0;
    return (p < Cc) ? x[((size_t)b * Nn + m) * Cc + p]
                    : h0[((size_t)b * Nn + m) * Hh + (p - Cc)];
}
__device__ __forceinline__ float comb1_val(const float* h1, int m, int col) {
    const int b = col >> 7, p = col & 127;
    return (p < Hh) ? g_ht0[((size_t)b * Nn + m) * Hh + p]
                    : h1[((size_t)b * Nn + m) * Hh + (p - Hh)];
}

__global__ void packC0_k(const float* __restrict__ x, const float* __restrict__ h0, int total)
{
    const int idx = blockIdx.x * blockDim.x + threadIdx.x;
    if (idx >= total) return;
    const int lane = idx & 31;
    const int jq   = (idx >> 5) & 15;
    const int kb   = (idx >> 9) & 255;
    const int nt   = idx >> 17;
    const int gg = lane >> 2, tt = lane & 3;
    const int na = nt * 256 + jq * 16 + gg;
    const int nb = na + 8;
    const int k0 = kb * 16 + tt * 2;
    uint4 v;
    v.x = h2pack(comb0_val(x, h0, k0,     na), comb0_val(x, h0, k0 + 1, na));
    v.y = h2pack(comb0_val(x, h0, k0 + 8, na), comb0_val(x, h0, k0 + 9, na));
    v.z = h2pack(comb0_val(x, h0, k0,     nb), comb0_val(x, h0, k0 + 1, nb));
    v.w = h2pack(comb0_val(x, h0, k0 + 8, nb), comb0_val(x, h0, k0 + 9, nb));
    g_combPh[idx] = v;
}
__global__ void packC1_k(const float* __restrict__ h1, int total)
{
    const int idx = blockIdx.x * blockDim.x + threadIdx.x;
    if (idx >= total) return;
    const int lane = idx & 31;
    const int jq   = (idx >> 5) & 15;
    const int kb   = (idx >> 9) & 255;
    const int nt   = idx >> 17;
    const int gg = lane >> 2, tt = lane & 3;
    const int na = nt * 256 + jq * 16 + gg;
    const int nb = na + 8;
    const int k0 = kb * 16 + tt * 2;
    uint4 v;
    v.x = h2pack(comb1_val(h1, k0,     na), comb1_val(h1, k0 + 1, na));
    v.y = h2pack(comb1_val(h1, k0 + 8, na), comb1_val(h1, k0 + 9, na));
    v.z = h2pack(comb1_val(h1, k0,     nb), comb1_val(h1, k0 + 1, nb));
    v.w = h2pack(comb1_val(h1, k0 + 8, nb), comb1_val(h1, k0 + 9, nb));
    g_combPh[idx] = v;
}

__global__ void packW_k(const float* __restrict__ W, int KPv, int total)
{
    const int idx = blockIdx.x * blockDim.x + threadIdx.x;
    if (idx >= total) return;
    const int lane = idx & 31;
    const int jq   = (idx >> 5) & 15;
    const int kb   = idx >> 9;
    const int gg = lane >> 2, tt = lane & 3;
    const int na = jq * 16 + gg;
    const int nb = na + 8;
    const int k0 = kb * 16 + tt * 2;
    auto wv = [&](int k, int n) -> float {
        return (k < KPv) ? W[(size_t)k * GH + n] : 0.f;
    };
    uint4 v;
    v.x = h2pack(wv(k0, na),     wv(k0 + 1, na));
    v.y = h2pack(wv(k0 + 8, na), wv(k0 + 9, na));
    v.z = h2pack(wv(k0, nb),     wv(k0 + 1, nb));
    v.w = h2pack(wv(k0 + 8, nb), wv(k0 + 9, nb));
    g_WtPh[idx] = v;
}

// ---------------------------------------------------------------------------
extern "C" void kernel_launch(void* const* d_in, const int* in_sizes, int n_in,
                              void* d_out, int out_size)
{
    (void)in_sizes; (void)n_in; (void)out_size;
    const float* G  = (const float*)d_in[0];
    const float* xt = (const float*)d_in[1];
    const float* h0 = (const float*)d_in[2];
    const float* h1 = (const float*)d_in[3];
    const float* c0 = (const float*)d_in[4];
    const float* c1 = (const float*)d_in[5];
    const float* W0 = (const float*)d_in[6];
    const float* b0 = (const float*)d_in[7];
    const float* W1 = (const float*)d_in[8];
    const float* b1 = (const float*)d_in[9];
    float* out = (float*)d_out;

    uint4 *GP, *combP, *suppP, *WtP;
    float *ht0;
    cudaGetSymbolAddress((void**)&GP,    g_GPh);
    cudaGetSymbolAddress((void**)&combP, g_combPh);
    cudaGetSymbolAddress((void**)&suppP, g_suppPh);
    cudaGetSymbolAddress((void**)&WtP,   g_WtPh);
    cudaGetSymbolAddress((void**)&ht0,   g_ht0);

    cudaFuncSetAttribute(gemm_fp16<0, P0>, cudaFuncAttributeMaxDynamicSharedMemorySize, SMEM_MAIN);
    cudaFuncSetAttribute(gemm_fp16<0, P1>, cudaFuncAttributeMaxDynamicSharedMemorySize, SMEM_MAIN);
    cudaFuncSetAttribute(gemm_fp16<1, P0>, cudaFuncAttributeMaxDynamicSharedMemorySize, SMEM_MAIN);

    const size_t S = (size_t)ROWS * Hh;   // 8388608 per output slot
    const int nktG32  = Nn / 32;          // 128 (32-K tiles, supp GEMM)
    const int nkt0_32 = 8;                // gates layer0, K padded 240 -> 256
    const int nkt1_32 = 12;               // gates layer1, K = 384
    const int nktOut0 = 16;               // 16-K blocks in suppP (layer0)
    const int nktOut1 = 24;

    // pack G (both layers)
    packG_k<<<(Kc * 32 * 256 * 8 * 32) / 256, 256>>>(G);

    // ---- layer 0 ----
    {
        const int tot = (NC0 / 256) * 256 * 16 * 32;   // nt=10
        packC0_k<<<(tot + 255) / 256, 256>>>(xt, h0, tot);
    }
    gemm_fp16<0, P0><<<dim3(NC0 / BN, Nn / BM, Kc), 256, SMEM_MAIN>>>(
        GP, combP, nktG32, suppP, nktOut0,
        nullptr, nullptr, nullptr, nullptr, nullptr, nullptr);
    {
        const int tot = nktOut0 * 16 * 32;
        packW_k<<<(tot + 255) / 256, 256>>>(W0, KP0, tot);
    }
    gemm_fp16<1, P0><<<dim3(1, ROWS / BM, 1), 256, SMEM_MAIN>>>(
        suppP, WtP, nkt0_32, nullptr, 0,
        b0, c0, out + S, nullptr, out + 3 * S, ht0);

    // ---- layer 1 ----
    {
        const int tot = (NC1 / 256) * 256 * 16 * 32;   // nt=16
        packC1_k<<<(tot + 255) / 256, 256>>>(h1, tot);
    }
    gemm_fp16<0, P1><<<dim3(NC1 / BN, Nn / BM, Kc), 256, SMEM_MAIN>>>(
        GP, combP, nktG32, suppP, nktOut1,
        nullptr, nullptr, nullptr, nullptr, nullptr, nullptr);
    {
        const int tot = nktOut1 * 16 * 32;
        packW_k<<<(tot + 255) / 256, 256>>>(W1, KP1, tot);
    }
    gemm_fp16<1, P0><<<dim3(1, ROWS / BM, 1), 256, SMEM_MAIN>>>(
        suppP, WtP, nkt1_32, nullptr, 0,
        b1, c1, out, out + 2 * S, out + 4 * S, nullptr);
}

// round 16
// speedup vs baseline: 1.3206x; 1.3206x over previous
#include <cuda_runtime.h>
#include <cuda_fp16.h>
#include <math.h>
#include <stdint.h>

// ---------------- problem constants ----------------
#define Nn    4096
#define Bb    32
#define Cc    16
#define Hh    64
#define Kc    3
#define P0    80
#define P1    128
#define NC0   (Bb*P0)     // 2560
#define NC1   (Bb*P1)     // 4096
#define KP0   (Kc*P0)     // 240
#define KP1   (Kc*P1)     // 384
#define GH    256
#define ROWS  (Bb*Nn)     // 131072

// ---------------- GEMM tiling (fp16 operands, fp32 accum) ----------------
// BK=64: stage = A(128x64) 16KB + B(64x256) 32KB = 48KB, 3 stages = 144KB
#define BM   128
#define BN   256
#define ASTG 16384
#define BSTG 32768
#define STG  (ASTG + BSTG)         // 49152
#define NSTG 3
#define SMEM_MAIN (NSTG * STG)     // 147456 (epilogue reuses 66.6KB)

// ---------------- scratch (__device__ globals, fragment-packed fp16) -------
// A for supp GEMM: [z(3)][mt(32)][kb16(256)][g16(8)][lane(32)] uint4
__device__ uint4 g_GPh   [(size_t)Kc * 32 * 256 * 8 * 32];     // 100.7 MB
// B (comb): [nt(<=16)][kb16(256)][jq(16)][lane(32)] uint4
__device__ uint4 g_combPh[(size_t)16 * 256 * 16 * 32];         // 33.5 MB
// A for gates GEMM: [mt(1024)][kb16(<=24)][g16(8)][lane(32)] uint4
__device__ uint4 g_suppPh[(size_t)1024 * 24 * 8 * 32];         // 100.7 MB
// B (W): [kb16(<=24)][jq(16)][lane(32)] uint4
__device__ uint4 g_WtPh  [(size_t)24 * 16 * 32];
__device__ float g_ht0   [(size_t)ROWS * Hh];                  // 33.5 MB

// ---------------- helpers ----------------
__device__ __forceinline__ float sigm(float x) { return 1.f / (1.f + expf(-x)); }

__device__ __forceinline__ uint32_t h2pack(float a, float b) {
    __half2 h = __halves2half2(__float2half_rn(a), __float2half_rn(b));
    return *reinterpret_cast<uint32_t*>(&h);
}

__device__ __forceinline__ void cp16(void* s, const void* g) {
    uint32_t a;
    asm("{ .reg .u64 t; cvta.to.shared.u64 t, %1; cvt.u32.u64 %0, t; }" : "=r"(a) : "l"(s));
    asm volatile("cp.async.cg.shared.global [%0], [%1], 16;" :: "r"(a), "l"(g));
}
#define CP_COMMIT() asm volatile("cp.async.commit_group;")
#define CP_WAIT1()  asm volatile("cp.async.wait_group 1;")
#define CP_WAIT0()  asm volatile("cp.async.wait_group 0;")

// fp16 MMA: D(f32) += A(f16) * B(f16); m16n8k16
#define MMAH(accq, af, b0, b1) \
    asm volatile("mma.sync.aligned.m16n8k16.row.col.f32.f16.f16.f32 " \
        "{%0,%1,%2,%3}, {%4,%5,%6,%7}, {%8,%9}, {%0,%1,%2,%3};" \
        : "+f"((accq)[0]), "+f"((accq)[1]), "+f"((accq)[2]), "+f"((accq)[3]) \
        : "r"((af).x), "r"((af).y), "r"((af).z), "r"((af).w), "r"(b0), "r"(b1))

// 32-MMA block for one k16 step: A frags afq[4], B frags bfq[4]
#define MMA_BLOCK(afq, bfq) do { \
    _Pragma("unroll") \
    for (int mi = 0; mi < 4; mi++) \
        _Pragma("unroll") \
        for (int jq = 0; jq < 4; jq++) { \
            MMAH(acc[mi][jq * 2],     (afq)[mi], (bfq)[jq].x, (bfq)[jq].y); \
            MMAH(acc[mi][jq * 2 + 1], (afq)[mi], (bfq)[jq].z, (bfq)[jq].w); \
        } \
} while (0)

#define LOAD_FRAGS(afq, bfq, sA, sB, s16) do { \
    _Pragma("unroll") \
    for (int mi = 0; mi < 4; mi++) (afq)[mi] = (sA)[(s16) * 256 + (wm * 4 + mi) * 32 + lane]; \
    _Pragma("unroll") \
    for (int jq = 0; jq < 4; jq++) (bfq)[jq] = (sB)[(s16) * 512 + (wn * 4 + jq) * 32 + lane]; \
} while (0)

// ---------------------------------------------------------------------------
// Packed-fragment fp16 GEMM, software-pipelined, BK=64 (four 16-K steps per
// iteration, ONE wait+sync per iteration). C[128x256] per CTA. 8 warps (2x4),
// warp tile 64x64. 3-stage cp.async ring of 48KB stages; register ping-pong on
// fragments: every 8-LDS batch issues under an independent 32-MMA block.
// MODE 0: emit supp as packed fp16 A-fragments for the gates GEMM.
// MODE 1: fused bias + LSTM.
// nkt in 64-K tiles (>=2); nktOut (MODE 0) in 16-K blocks.
// ---------------------------------------------------------------------------
template<int MODE, int PC>
__global__ void __launch_bounds__(256, 1)
gemm_fp16(const uint4* __restrict__ Ap, const uint4* __restrict__ Bp,
          int nkt, uint4* __restrict__ outP, int nktOut,
          const float* __restrict__ bias, const float* __restrict__ cpre,
          float* __restrict__ ho1, float* __restrict__ ho2,
          float* __restrict__ co,  float* __restrict__ hscr)
{
    extern __shared__ char smem[];
    const int tid  = threadIdx.x;
    const int wid  = tid >> 5, lane = tid & 31;
    const int wm   = wid >> 2, wn = wid & 3;
    const int bm0  = blockIdx.y * BM;
    const int bn0  = blockIdx.x * BN;
    const int zz   = blockIdx.z;

    // uint4 units: A kb16 block = 256, B kb16 block = 512 (k64 tile: 1024 / 2048)
    const uint4* Abase = Ap + ((size_t)zz * gridDim.y + blockIdx.y) * (size_t)(4 * nkt) * 256;
    const uint4* Bbase = Bp + (size_t)blockIdx.x * (size_t)(4 * nkt) * 512;

    float acc[4][8][4];
    #pragma unroll
    for (int ai = 0; ai < 4; ai++)
        #pragma unroll
        for (int bj = 0; bj < 8; bj++)
            #pragma unroll
            for (int cq = 0; cq < 4; cq++) acc[ai][bj][cq] = 0.f;

    auto pf = [&](int sg, int kt) {
        char* sA = smem + sg * STG;
        char* sB = sA + ASTG;
        const uint4* ag = Abase + (size_t)kt * 1024;
        const uint4* bg = Bbase + (size_t)kt * 2048;
        #pragma unroll
        for (int i = 0; i < 4; i++)
            cp16(sA + (tid + i * 256) * 16, ag + tid + i * 256);
        #pragma unroll
        for (int i = 0; i < 8; i++)
            cp16(sB + (tid + i * 256) * 16, bg + tid + i * 256);
    };

    pf(0, 0); CP_COMMIT();
    if (nkt > 1) pf(1, 1);
    CP_COMMIT();
    CP_WAIT1();
    __syncthreads();

    uint4 afA[4], bfA[4], afB[4], bfB[4];   // ping-pong fragment buffers

    {   // prologue: step-0 frags of tile 0
        const uint4* sA = (const uint4*)(smem);
        const uint4* sB = (const uint4*)(smem + ASTG);
        LOAD_FRAGS(afA, bfA, sA, sB, 0);
    }

    int sg = 0;
    for (int kt = 0; kt < nkt; kt++) {
        const uint4* sA = (const uint4*)(smem + sg * STG);
        const uint4* sB = (const uint4*)(smem + sg * STG + ASTG);

        // step 1 frags under step-0 MMAs
        LOAD_FRAGS(afB, bfB, sA, sB, 1);
        MMA_BLOCK(afA, bfA);

        // step 2 frags under step-1 MMAs
        LOAD_FRAGS(afA, bfA, sA, sB, 2);
        MMA_BLOCK(afB, bfB);

        // prefetch tile kt+2 into the stage consumed at iteration kt-1
        if (kt + 2 < nkt) pf((kt + 2) % NSTG, kt + 2);
        CP_COMMIT();

        // step 3 frags under step-2 MMAs
        LOAD_FRAGS(afB, bfB, sA, sB, 3);
        MMA_BLOCK(afA, bfA);

        if (kt + 1 < nkt) {
            CP_WAIT1();
            __syncthreads();
            const int sg2 = (kt + 1) % NSTG;
            const uint4* sA2 = (const uint4*)(smem + sg2 * STG);
            const uint4* sB2 = (const uint4*)(smem + sg2 * STG + ASTG);
            // next tile's step-0 frags under step-3 MMAs
            LOAD_FRAGS(afA, bfA, sA2, sB2, 0);
        }
        MMA_BLOCK(afB, bfB);

        if (++sg == NSTG) sg = 0;
    }
    CP_WAIT0();
    __syncthreads();

    // ---------------- epilogue (staged per 64-row half) ----------------
    const int lq = lane >> 2, lr = lane & 3;
    float* sC = (float*)smem;                 // [64][260] = 66560 B

    for (int h = 0; h < 2; h++) {
        if (wm == h) {
            #pragma unroll
            for (int mi = 0; mi < 4; mi++)
                #pragma unroll
                for (int j = 0; j < 8; j++) {
                    const int r0 = mi * 16 + lq;
                    const int c0 = wn * 64 + j * 8 + lr * 2;
                    sC[r0 * 260 + c0]           = acc[mi][j][0];
                    sC[r0 * 260 + c0 + 1]       = acc[mi][j][1];
                    sC[(r0 + 8) * 260 + c0]     = acc[mi][j][2];
                    sC[(r0 + 8) * 260 + c0 + 1] = acc[mi][j][3];
                }
        }
        __syncthreads();

        if constexpr (MODE == 0) {
            // emit packed fp16 A-fragments for the gates GEMM
            // 2048 uint4 per half: [lkb(16)][g16h(4)][lane(32)]
            #pragma unroll 4
            for (int it = 0; it < 8; it++) {
                const int idx  = it * 256 + tid;       // 0..2047
                const int ln2  = idx & 31;
                const int g16h = (idx >> 5) & 3;
                const int lkb  = idx >> 7;             // 0..15
                const int gg = ln2 >> 2, tt = ln2 & 3;
                const int rl0 = g16h * 16 + gg;        // local row in half
                const int c0  = lkb * 16 + tt * 2;
                uint4 ha;
                ha.x = h2pack(sC[rl0 * 260 + c0],           sC[rl0 * 260 + c0 + 1]);
                ha.y = h2pack(sC[(rl0 + 8) * 260 + c0],     sC[(rl0 + 8) * 260 + c0 + 1]);
                ha.z = h2pack(sC[rl0 * 260 + c0 + 8],       sC[rl0 * 260 + c0 + 9]);
                ha.w = h2pack(sC[(rl0 + 8) * 260 + c0 + 8], sC[(rl0 + 8) * 260 + c0 + 9]);
                const int gcb  = bn0 + lkb * 16;       // 16-aligned col block
                const int bi   = gcb / PC;
                const int kidx = zz * PC + (gcb - bi * PC);
                const int kt2  = kidx >> 4;
                const int mtg  = bi * (Nn / 128) + (bm0 >> 7);
                const int g16g = h * 4 + g16h;
                const size_t f4i =
                    (((size_t)mtg * nktOut + kt2) * 8 + g16g) * 32 + ln2;
                outP[f4i] = ha;
            }
        } else {
            // fused bias + LSTM; cols 0..63=i, 64..127=f, 128..191=o, 192..255=g
            #pragma unroll 4
            for (int it = 0; it < 16; it++) {
                const int idx  = it * 256 + tid;       // 0..4095
                const int row  = idx >> 6;             // 0..63
                const int hc   = idx & 63;
                const float gi = sC[row * 260 + hc]        + __ldg(bias + hc);
                const float gf = sC[row * 260 + 64 + hc]   + __ldg(bias + 64 + hc);
                const float go = sC[row * 260 + 128 + hc]  + __ldg(bias + 128 + hc);
                const float gg = sC[row * 260 + 192 + hc]  + __ldg(bias + 192 + hc);
                const size_t m  = (size_t)bm0 + h * 64 + row;
                const size_t ix = m * Hh + hc;
                const float ct = sigm(gf) * cpre[ix] + sigm(gi) * tanhf(gg);
                const float ht = sigm(go) * tanhf(ct);
                ho1[ix] = ht;
                if (ho2)  ho2[ix]  = ht;
                co[ix] = ct;
                if (hscr) hscr[ix] = ht;
            }
        }
        __syncthreads();
    }
}

// ---------------------------------------------------------------------------
// pack kernels (fp16 fragments, round-to-nearest)
// ---------------------------------------------------------------------------
__global__ void packG_k(const float* __restrict__ G)
{
    const int idx = blockIdx.x * blockDim.x + threadIdx.x;
    if (idx >= Kc * 32 * 256 * 8 * 32) return;
    const int lane = idx & 31;
    const int g16  = (idx >> 5) & 7;
    const int kb   = (idx >> 8) & 255;
    const int mt   = (idx >> 16) & 31;
    const int zi   = idx >> 21;
    const int gg = lane >> 2, tt = lane & 3;
    const int r = mt * 128 + g16 * 16 + gg;
    const int c = kb * 16 + tt * 2;
    const float* Gz = G + (size_t)zi * Nn * Nn;
    uint4 v;
    v.x = h2pack(Gz[(size_t)r * Nn + c],           Gz[(size_t)r * Nn + c + 1]);
    v.y = h2pack(Gz[(size_t)(r + 8) * Nn + c],     Gz[(size_t)(r + 8) * Nn + c + 1]);
    v.z = h2pack(Gz[(size_t)r * Nn + c + 8],       Gz[(size_t)r * Nn + c + 9]);
    v.w = h2pack(Gz[(size_t)(r + 8) * Nn + c + 8], Gz[(size_t)(r + 8) * Nn + c + 9]);
    g_GPh[idx] = v;
}

__device__ __forceinline__ float comb0_val(const float* x, const float* h0, int m, int col) {
    const int b = col / P0, p = col - b * P0;
    return (p < Cc) ? x[((size_t)b * Nn + m) * Cc + p]
                    : h0[((size_t)b * Nn + m) * Hh + (p - Cc)];
}
__device__ __forceinline__ float comb1_val(const float* h1, int m, int col) {
    const int b = col >> 7, p = col & 127;
    return (p < Hh) ? g_ht0[((size_t)b * Nn + m) * Hh + p]
                    : h1[((size_t)b * Nn + m) * Hh + (p - Hh)];
}

__global__ void packC0_k(const float* __restrict__ x, const float* __restrict__ h0, int total)
{
    const int idx = blockIdx.x * blockDim.x + threadIdx.x;
    if (idx >= total) return;
    const int lane = idx & 31;
    const int jq   = (idx >> 5) & 15;
    const int kb   = (idx >> 9) & 255;
    const int nt   = idx >> 17;
    const int gg = lane >> 2, tt = lane & 3;
    const int na = nt * 256 + jq * 16 + gg;
    const int nb = na + 8;
    const int k0 = kb * 16 + tt * 2;
    uint4 v;
    v.x = h2pack(comb0_val(x, h0, k0,     na), comb0_val(x, h0, k0 + 1, na));
    v.y = h2pack(comb0_val(x, h0, k0 + 8, na), comb0_val(x, h0, k0 + 9, na));
    v.z = h2pack(comb0_val(x, h0, k0,     nb), comb0_val(x, h0, k0 + 1, nb));
    v.w = h2pack(comb0_val(x, h0, k0 + 8, nb), comb0_val(x, h0, k0 + 9, nb));
    g_combPh[idx] = v;
}
__global__ void packC1_k(const float* __restrict__ h1, int total)
{
    const int idx = blockIdx.x * blockDim.x + threadIdx.x;
    if (idx >= total) return;
    const int lane = idx & 31;
    const int jq   = (idx >> 5) & 15;
    const int kb   = (idx >> 9) & 255;
    const int nt   = idx >> 17;
    const int gg = lane >> 2, tt = lane & 3;
    const int na = nt * 256 + jq * 16 + gg;
    const int nb = na + 8;
    const int k0 = kb * 16 + tt * 2;
    uint4 v;
    v.x = h2pack(comb1_val(h1, k0,     na), comb1_val(h1, k0 + 1, na));
    v.y = h2pack(comb1_val(h1, k0 + 8, na), comb1_val(h1, k0 + 9, na));
    v.z = h2pack(comb1_val(h1, k0,     nb), comb1_val(h1, k0 + 1, nb));
    v.w = h2pack(comb1_val(h1, k0 + 8, nb), comb1_val(h1, k0 + 9, nb));
    g_combPh[idx] = v;
}

__global__ void packW_k(const float* __restrict__ W, int KPv, int total)
{
    const int idx = blockIdx.x * blockDim.x + threadIdx.x;
    if (idx >= total) return;
    const int lane = idx & 31;
    const int jq   = (idx >> 5) & 15;
    const int kb   = idx >> 9;
    const int gg = lane >> 2, tt = lane & 3;
    const int na = jq * 16 + gg;
    const int nb = na + 8;
    const int k0 = kb * 16 + tt * 2;
    auto wv = [&](int k, int n) -> float {
        return (k < KPv) ? W[(size_t)k * GH + n] : 0.f;
    };
    uint4 v;
    v.x = h2pack(wv(k0, na),     wv(k0 + 1, na));
    v.y = h2pack(wv(k0 + 8, na), wv(k0 + 9, na));
    v.z = h2pack(wv(k0, nb),     wv(k0 + 1, nb));
    v.w = h2pack(wv(k0 + 8, nb), wv(k0 + 9, nb));
    g_WtPh[idx] = v;
}

// ---------------------------------------------------------------------------
extern "C" void kernel_launch(void* const* d_in, const int* in_sizes, int n_in,
                              void* d_out, int out_size)
{
    (void)in_sizes; (void)n_in; (void)out_size;
    const float* G  = (const float*)d_in[0];
    const float* xt = (const float*)d_in[1];
    const float* h0 = (const float*)d_in[2];
    const float* h1 = (const float*)d_in[3];
    const float* c0 = (const float*)d_in[4];
    const float* c1 = (const float*)d_in[5];
    const float* W0 = (const float*)d_in[6];
    const float* b0 = (const float*)d_in[7];
    const float* W1 = (const float*)d_in[8];
    const float* b1 = (const float*)d_in[9];
    float* out = (float*)d_out;

    uint4 *GP, *combP, *suppP, *WtP;
    float *ht0;
    cudaGetSymbolAddress((void**)&GP,    g_GPh);
    cudaGetSymbolAddress((void**)&combP, g_combPh);
    cudaGetSymbolAddress((void**)&suppP, g_suppPh);
    cudaGetSymbolAddress((void**)&WtP,   g_WtPh);
    cudaGetSymbolAddress((void**)&ht0,   g_ht0);

    cudaFuncSetAttribute(gemm_fp16<0, P0>, cudaFuncAttributeMaxDynamicSharedMemorySize, SMEM_MAIN);
    cudaFuncSetAttribute(gemm_fp16<0, P1>, cudaFuncAttributeMaxDynamicSharedMemorySize, SMEM_MAIN);
    cudaFuncSetAttribute(gemm_fp16<1, P0>, cudaFuncAttributeMaxDynamicSharedMemorySize, SMEM_MAIN);

    const size_t S = (size_t)ROWS * Hh;   // 8388608 per output slot
    const int nktG64  = Nn / 64;          // 64 (64-K tiles, supp GEMM)
    const int nkt0_64 = 4;                // gates layer0, K padded 240 -> 256
    const int nkt1_64 = 6;                // gates layer1, K = 384
    const int nktOut0 = 16;               // 16-K blocks in suppP (layer0)
    const int nktOut1 = 24;

    // pack G (both layers)
    packG_k<<<(Kc * 32 * 256 * 8 * 32) / 256, 256>>>(G);

    // ---- layer 0 ----
    {
        const int tot = (NC0 / 256) * 256 * 16 * 32;   // nt=10
        packC0_k<<<(tot + 255) / 256, 256>>>(xt, h0, tot);
    }
    gemm_fp16<0, P0><<<dim3(NC0 / BN, Nn / BM, Kc), 256, SMEM_MAIN>>>(
        GP, combP, nktG64, suppP, nktOut0,
        nullptr, nullptr, nullptr, nullptr, nullptr, nullptr);
    {
        const int tot = nktOut0 * 16 * 32;
        packW_k<<<(tot + 255) / 256, 256>>>(W0, KP0, tot);
    }
    gemm_fp16<1, P0><<<dim3(1, ROWS / BM, 1), 256, SMEM_MAIN>>>(
        suppP, WtP, nkt0_64, nullptr, 0,
        b0, c0, out + S, nullptr, out + 3 * S, ht0);

    // ---- layer 1 ----
    {
        const int tot = (NC1 / 256) * 256 * 16 * 32;   // nt=16
        packC1_k<<<(tot + 255) / 256, 256>>>(h1, tot);
    }
    gemm_fp16<0, P1><<<dim3(NC1 / BN, Nn / BM, Kc), 256, SMEM_MAIN>>>(
        GP, combP, nktG64, suppP, nktOut1,
        nullptr, nullptr, nullptr, nullptr, nullptr, nullptr);
    {
        const int tot = nktOut1 * 16 * 32;
        packW_k<<<(tot + 255) / 256, 256>>>(W1, KP1, tot);
    }
    gemm_fp16<1, P0><<<dim3(1, ROWS / BM, 1), 256, SMEM_MAIN>>>(
        suppP, WtP, nkt1_64, nullptr, 0,
        b1, c1, out, out + 2 * S, out + 4 * S, nullptr);
}

// round 17
// speedup vs baseline: 1.3933x; 1.0551x over previous
#include <cuda_runtime.h>
#include <cuda_fp16.h>
#include <math.h>
#include <stdint.h>

// ---------------- problem constants ----------------
#define Nn    4096
#define Bb    32
#define Cc    16
#define Hh    64
#define Kc    3
#define P0    80
#define P1    128
#define NC0   (Bb*P0)     // 2560
#define NC1   (Bb*P1)     // 4096
#define KP0   (Kc*P0)     // 240
#define KP1   (Kc*P1)     // 384
#define GH    256
#define ROWS  (Bb*Nn)     // 131072

// ---------------- GEMM tiling (fp16 operands, fp32 accum) ----------------
#define BM   128
#define BN   256
#define ASTG 8192                  // 128x32 fp16 packed A
#define BSTG 16384                 // 32x256 fp16 packed B
#define STG  (ASTG + BSTG)         // 24576
#define SMEM_MAIN (4 * STG)        // 98304

// ---------------- scratch (__device__ globals, fragment-packed fp16) -------
// A for supp GEMM: [z(3)][mt(32)][kb16(256)][g16(8)][lane(32)] uint4
__device__ uint4 g_GPh   [(size_t)Kc * 32 * 256 * 8 * 32];     // 100.7 MB
// B (comb): [nt(<=16)][kb16(256)][jq(16)][lane(32)] uint4
__device__ uint4 g_combPh[(size_t)16 * 256 * 16 * 32];         // 33.5 MB
// A for gates GEMM: [mt(1024)][kb16(<=24)][g16(8)][lane(32)] uint4
__device__ uint4 g_suppPh[(size_t)1024 * 24 * 8 * 32];         // 100.7 MB
// B (W): 40 kb16-blocks: layer0 at [0..15], layer1 at [16..39]
__device__ uint4 g_WtPh  [(size_t)40 * 16 * 32];
__device__ float g_ht0   [(size_t)ROWS * Hh];                  // 33.5 MB

// ---------------- helpers ----------------
__device__ __forceinline__ float sigm(float x) { return 1.f / (1.f + expf(-x)); }

__device__ __forceinline__ uint32_t h2pack(float a, float b) {
    __half2 h = __halves2half2(__float2half_rn(a), __float2half_rn(b));
    return *reinterpret_cast<uint32_t*>(&h);
}

__device__ __forceinline__ void cp16(void* s, const void* g) {
    uint32_t a;
    asm("{ .reg .u64 t; cvta.to.shared.u64 t, %1; cvt.u32.u64 %0, t; }" : "=r"(a) : "l"(s));
    asm volatile("cp.async.cg.shared.global [%0], [%1], 16;" :: "r"(a), "l"(g));
}
#define CP_COMMIT() asm volatile("cp.async.commit_group;")
#define CP_WAIT2()  asm volatile("cp.async.wait_group 2;")
#define CP_WAIT0()  asm volatile("cp.async.wait_group 0;")

// fp16 MMA: D(f32) += A(f16) * B(f16); m16n8k16
#define MMAH(accq, af, b0, b1) \
    asm volatile("mma.sync.aligned.m16n8k16.row.col.f32.f16.f16.f32 " \
        "{%0,%1,%2,%3}, {%4,%5,%6,%7}, {%8,%9}, {%0,%1,%2,%3};" \
        : "+f"((accq)[0]), "+f"((accq)[1]), "+f"((accq)[2]), "+f"((accq)[3]) \
        : "r"((af).x), "r"((af).y), "r"((af).z), "r"((af).w), "r"(b0), "r"(b1))

// ---------------------------------------------------------------------------
// Packed-fragment fp16 GEMM, software-pipelined (the proven 2012us mainloop).
// C[128x256] per CTA; K in 32-wide tiles. 8 warps (2x4), warp tile 64x64.
// Register ping-pong: every 8-LDS batch issues under an independent 32-MMA
// block. 4-stage cp.async ring (A+B, 24KB/stage).
// MODE 0: DIRECT-REGISTER epilogue -> packed fp16 A-fragments (no smem stage).
// MODE 1: smem-staged fused bias + LSTM epilogue.
// nkt in 32-K tiles; nktOut (MODE 0) in 16-K blocks.
// ---------------------------------------------------------------------------
template<int MODE, int PC>
__global__ void __launch_bounds__(256, 1)
gemm_fp16(const uint4* __restrict__ Ap, const uint4* __restrict__ Bp,
          int nkt, uint4* __restrict__ outP, int nktOut,
          const float* __restrict__ bias, const float* __restrict__ cpre,
          float* __restrict__ ho1, float* __restrict__ ho2,
          float* __restrict__ co,  float* __restrict__ hscr)
{
    extern __shared__ char smem[];
    const int tid  = threadIdx.x;
    const int wid  = tid >> 5, lane = tid & 31;
    const int wm   = wid >> 2, wn = wid & 3;
    const int bm0  = blockIdx.y * BM;
    const int bn0  = blockIdx.x * BN;
    const int zz   = blockIdx.z;

    // uint4 units: A kb16 block = 256, B kb16 block = 512
    const uint4* Abase = Ap + ((size_t)zz * gridDim.y + blockIdx.y) * (size_t)(2 * nkt) * 256;
    const uint4* Bbase = Bp + (size_t)blockIdx.x * (size_t)(2 * nkt) * 512;

    float acc[4][8][4];
    #pragma unroll
    for (int ai = 0; ai < 4; ai++)
        #pragma unroll
        for (int bj = 0; bj < 8; bj++)
            #pragma unroll
            for (int cq = 0; cq < 4; cq++) acc[ai][bj][cq] = 0.f;

    auto pf = [&](int sg, int kt) {
        char* sA = smem + sg * STG;
        char* sB = sA + ASTG;
        const uint4* ag = Abase + (size_t)kt * 512;
        const uint4* bg = Bbase + (size_t)kt * 1024;
        cp16(sA + tid * 16,         ag + tid);
        cp16(sA + (tid + 256) * 16, ag + tid + 256);
        #pragma unroll
        for (int i = 0; i < 4; i++)
            cp16(sB + (tid + i * 256) * 16, bg + tid + i * 256);
    };

    pf(0, 0); CP_COMMIT();
    if (nkt > 1) pf(1, 1);
    CP_COMMIT();
    if (nkt > 2) pf(2, 2);
    CP_COMMIT();
    CP_WAIT2();
    __syncthreads();

    uint4 af0[4], bf0[4], af1[4], bf1[4];   // fixed-role frag buffers

    {   // prologue: k2=0 frags of tile 0
        const uint4* sA = (const uint4*)(smem);
        const uint4* sB = (const uint4*)(smem + ASTG);
        #pragma unroll
        for (int mi = 0; mi < 4; mi++) af0[mi] = sA[(wm * 4 + mi) * 32 + lane];
        #pragma unroll
        for (int jq = 0; jq < 4; jq++) bf0[jq] = sB[(wn * 4 + jq) * 32 + lane];
    }

    for (int kt = 0; kt < nkt; kt++) {
        const int sg = kt & 3;
        const uint4* sA = (const uint4*)(smem + sg * STG);
        const uint4* sB = (const uint4*)(smem + sg * STG + ASTG);

        // load k2=1 frags (hidden under the k2=0 MMA block below)
        #pragma unroll
        for (int mi = 0; mi < 4; mi++) af1[mi] = sA[256 + (wm * 4 + mi) * 32 + lane];
        #pragma unroll
        for (int jq = 0; jq < 4; jq++) bf1[jq] = sB[512 + (wn * 4 + jq) * 32 + lane];

        // MMAs for k2=0
        #pragma unroll
        for (int mi = 0; mi < 4; mi++)
            #pragma unroll
            for (int jq = 0; jq < 4; jq++) {
                MMAH(acc[mi][jq * 2],     af0[mi], bf0[jq].x, bf0[jq].y);
                MMAH(acc[mi][jq * 2 + 1], af0[mi], bf0[jq].z, bf0[jq].w);
            }

        if (kt + 3 < nkt) pf((kt + 3) & 3, kt + 3);
        CP_COMMIT();

        if (kt + 1 < nkt) {
            CP_WAIT2();
            __syncthreads();
            const int sg2 = (kt + 1) & 3;
            const uint4* sA2 = (const uint4*)(smem + sg2 * STG);
            const uint4* sB2 = (const uint4*)(smem + sg2 * STG + ASTG);
            // next tile's k2=0 frags (hidden under the k2=1 MMA block)
            #pragma unroll
            for (int mi = 0; mi < 4; mi++) af0[mi] = sA2[(wm * 4 + mi) * 32 + lane];
            #pragma unroll
            for (int jq = 0; jq < 4; jq++) bf0[jq] = sB2[(wn * 4 + jq) * 32 + lane];
        }

        // MMAs for k2=1
        #pragma unroll
        for (int mi = 0; mi < 4; mi++)
            #pragma unroll
            for (int jq = 0; jq < 4; jq++) {
                MMAH(acc[mi][jq * 2],     af1[mi], bf1[jq].x, bf1[jq].y);
                MMAH(acc[mi][jq * 2 + 1], af1[mi], bf1[jq].z, bf1[jq].w);
            }
    }
    CP_WAIT0();
    __syncthreads();

    if constexpr (MODE == 0) {
        // ---------------- DIRECT-REGISTER epilogue ----------------
        // acc[mi][2jp..2jp+1] is exactly one packed-A uint4; target lane == lane.
        // Each store: 32-lane x 16B = 512B coalesced.
        const int g16base = wm * 4;
        const int mtrow   = bm0 >> 7;
        #pragma unroll
        for (int jp = 0; jp < 4; jp++) {
            const int gcb  = bn0 + wn * 64 + jp * 16;   // 16-aligned col block
            const int bi   = gcb / PC;
            const int kidx = zz * PC + (gcb - bi * PC);
            const int kt2  = kidx >> 4;
            const int mtg  = bi * (Nn / 128) + mtrow;
            const size_t base = (((size_t)mtg * nktOut + kt2) * 8 + g16base) * 32 + lane;
            #pragma unroll
            for (int mi = 0; mi < 4; mi++) {
                uint4 ha;
                ha.x = h2pack(acc[mi][jp * 2][0],     acc[mi][jp * 2][1]);
                ha.y = h2pack(acc[mi][jp * 2][2],     acc[mi][jp * 2][3]);
                ha.z = h2pack(acc[mi][jp * 2 + 1][0], acc[mi][jp * 2 + 1][1]);
                ha.w = h2pack(acc[mi][jp * 2 + 1][2], acc[mi][jp * 2 + 1][3]);
                outP[base + (size_t)mi * 32] = ha;
            }
        }
    } else {
        // ---------------- smem-staged fused bias + LSTM ----------------
        const int lq = lane >> 2, lr = lane & 3;
        float* sC = (float*)smem;                 // [64][260] = 66560 B

        for (int h = 0; h < 2; h++) {
            if (wm == h) {
                #pragma unroll
                for (int mi = 0; mi < 4; mi++)
                    #pragma unroll
                    for (int j = 0; j < 8; j++) {
                        const int r0 = mi * 16 + lq;
                        const int c0 = wn * 64 + j * 8 + lr * 2;
                        sC[r0 * 260 + c0]           = acc[mi][j][0];
                        sC[r0 * 260 + c0 + 1]       = acc[mi][j][1];
                        sC[(r0 + 8) * 260 + c0]     = acc[mi][j][2];
                        sC[(r0 + 8) * 260 + c0 + 1] = acc[mi][j][3];
                    }
            }
            __syncthreads();

            // cols 0..63=i, 64..127=f, 128..191=o, 192..255=g
            #pragma unroll 4
            for (int it = 0; it < 16; it++) {
                const int idx  = it * 256 + tid;       // 0..4095
                const int row  = idx >> 6;             // 0..63
                const int hc   = idx & 63;
                const float gi = sC[row * 260 + hc]        + __ldg(bias + hc);
                const float gf = sC[row * 260 + 64 + hc]   + __ldg(bias + 64 + hc);
                const float go = sC[row * 260 + 128 + hc]  + __ldg(bias + 128 + hc);
                const float gg = sC[row * 260 + 192 + hc]  + __ldg(bias + 192 + hc);
                const size_t m  = (size_t)bm0 + h * 64 + row;
                const size_t ix = m * Hh + hc;
                const float ct = sigm(gf) * cpre[ix] + sigm(gi) * tanhf(gg);
                const float ht = sigm(go) * tanhf(ct);
                ho1[ix] = ht;
                if (ho2)  ho2[ix]  = ht;
                co[ix] = ct;
                if (hscr) hscr[ix] = ht;
            }
            __syncthreads();
        }
    }
}

// ---------------------------------------------------------------------------
// pack kernels (fp16 fragments, round-to-nearest)
// ---------------------------------------------------------------------------
__global__ void packG_k(const float* __restrict__ G)
{
    const int idx = blockIdx.x * blockDim.x + threadIdx.x;
    if (idx >= Kc * 32 * 256 * 8 * 32) return;
    const int lane = idx & 31;
    const int g16  = (idx >> 5) & 7;
    const int kb   = (idx >> 8) & 255;
    const int mt   = (idx >> 16) & 31;
    const int zi   = idx >> 21;
    const int gg = lane >> 2, tt = lane & 3;
    const int r = mt * 128 + g16 * 16 + gg;
    const int c = kb * 16 + tt * 2;
    const float* Gz = G + (size_t)zi * Nn * Nn;
    uint4 v;
    v.x = h2pack(Gz[(size_t)r * Nn + c],           Gz[(size_t)r * Nn + c + 1]);
    v.y = h2pack(Gz[(size_t)(r + 8) * Nn + c],     Gz[(size_t)(r + 8) * Nn + c + 1]);
    v.z = h2pack(Gz[(size_t)r * Nn + c + 8],       Gz[(size_t)r * Nn + c + 9]);
    v.w = h2pack(Gz[(size_t)(r + 8) * Nn + c + 8], Gz[(size_t)(r + 8) * Nn + c + 9]);
    g_GPh[idx] = v;
}

__device__ __forceinline__ float comb0_val(const float* x, const float* h0, int m, int col) {
    const int b = col / P0, p = col - b * P0;
    return (p < Cc) ? x[((size_t)b * Nn + m) * Cc + p]
                    : h0[((size_t)b * Nn + m) * Hh + (p - Cc)];
}
__device__ __forceinline__ float comb1_val(const float* h1, int m, int col) {
    const int b = col >> 7, p = col & 127;
    return (p < Hh) ? g_ht0[((size_t)b * Nn + m) * Hh + p]
                    : h1[((size_t)b * Nn + m) * Hh + (p - Hh)];
}

__global__ void packC0_k(const float* __restrict__ x, const float* __restrict__ h0, int total)
{
    const int idx = blockIdx.x * blockDim.x + threadIdx.x;
    if (idx >= total) return;
    const int lane = idx & 31;
    const int jq   = (idx >> 5) & 15;
    const int kb   = (idx >> 9) & 255;
    const int nt   = idx >> 17;
    const int gg = lane >> 2, tt = lane & 3;
    const int na = nt * 256 + jq * 16 + gg;
    const int nb = na + 8;
    const int k0 = kb * 16 + tt * 2;
    uint4 v;
    v.x = h2pack(comb0_val(x, h0, k0,     na), comb0_val(x, h0, k0 + 1, na));
    v.y = h2pack(comb0_val(x, h0, k0 + 8, na), comb0_val(x, h0, k0 + 9, na));
    v.z = h2pack(comb0_val(x, h0, k0,     nb), comb0_val(x, h0, k0 + 1, nb));
    v.w = h2pack(comb0_val(x, h0, k0 + 8, nb), comb0_val(x, h0, k0 + 9, nb));
    g_combPh[idx] = v;
}
__global__ void packC1_k(const float* __restrict__ h1, int total)
{
    const int idx = blockIdx.x * blockDim.x + threadIdx.x;
    if (idx >= total) return;
    const int lane = idx & 31;
    const int jq   = (idx >> 5) & 15;
    const int kb   = (idx >> 9) & 255;
    const int nt   = idx >> 17;
    const int gg = lane >> 2, tt = lane & 3;
    const int na = nt * 256 + jq * 16 + gg;
    const int nb = na + 8;
    const int k0 = kb * 16 + tt * 2;
    uint4 v;
    v.x = h2pack(comb1_val(h1, k0,     na), comb1_val(h1, k0 + 1, na));
    v.y = h2pack(comb1_val(h1, k0 + 8, na), comb1_val(h1, k0 + 9, na));
    v.z = h2pack(comb1_val(h1, k0,     nb), comb1_val(h1, k0 + 1, nb));
    v.w = h2pack(comb1_val(h1, k0 + 8, nb), comb1_val(h1, k0 + 9, nb));
    g_combPh[idx] = v;
}

// W -> B-fragments at block offset kbOff; rows k >= KPv zero-filled.
__global__ void packW_k(const float* __restrict__ W, int KPv, int kbOff, int total)
{
    const int idx = blockIdx.x * blockDim.x + threadIdx.x;
    if (idx >= total) return;
    const int lane = idx & 31;
    const int jq   = (idx >> 5) & 15;
    const int kb   = idx >> 9;
    const int gg = lane >> 2, tt = lane & 3;
    const int na = jq * 16 + gg;
    const int nb = na + 8;
    const int k0 = kb * 16 + tt * 2;
    auto wv = [&](int k, int n) -> float {
        return (k < KPv) ? W[(size_t)k * GH + n] : 0.f;
    };
    uint4 v;
    v.x = h2pack(wv(k0, na),     wv(k0 + 1, na));
    v.y = h2pack(wv(k0 + 8, na), wv(k0 + 9, na));
    v.z = h2pack(wv(k0, nb),     wv(k0 + 1, nb));
    v.w = h2pack(wv(k0 + 8, nb), wv(k0 + 9, nb));
    g_WtPh[(size_t)kbOff * 512 + idx] = v;
}

// ---------------------------------------------------------------------------
extern "C" void kernel_launch(void* const* d_in, const int* in_sizes, int n_in,
                              void* d_out, int out_size)
{
    (void)in_sizes; (void)n_in; (void)out_size;
    const float* G  = (const float*)d_in[0];
    const float* xt = (const float*)d_in[1];
    const float* h0 = (const float*)d_in[2];
    const float* h1 = (const float*)d_in[3];
    const float* c0 = (const float*)d_in[4];
    const float* c1 = (const float*)d_in[5];
    const float* W0 = (const float*)d_in[6];
    const float* b0 = (const float*)d_in[7];
    const float* W1 = (const float*)d_in[8];
    const float* b1 = (const float*)d_in[9];
    float* out = (float*)d_out;

    uint4 *GP, *combP, *suppP, *WtP;
    float *ht0;
    cudaGetSymbolAddress((void**)&GP,    g_GPh);
    cudaGetSymbolAddress((void**)&combP, g_combPh);
    cudaGetSymbolAddress((void**)&suppP, g_suppPh);
    cudaGetSymbolAddress((void**)&WtP,   g_WtPh);
    cudaGetSymbolAddress((void**)&ht0,   g_ht0);

    cudaFuncSetAttribute(gemm_fp16<0, P0>, cudaFuncAttributeMaxDynamicSharedMemorySize, SMEM_MAIN);
    cudaFuncSetAttribute(gemm_fp16<0, P1>, cudaFuncAttributeMaxDynamicSharedMemorySize, SMEM_MAIN);
    cudaFuncSetAttribute(gemm_fp16<1, P0>, cudaFuncAttributeMaxDynamicSharedMemorySize, SMEM_MAIN);

    const size_t S = (size_t)ROWS * Hh;   // 8388608 per output slot
    const int nktG32  = Nn / 32;          // 128 (32-K tiles, supp GEMM)
    const int nkt0_32 = 8;                // gates layer0, K padded 240 -> 256
    const int nkt1_32 = 12;               // gates layer1, K = 384
    const int nktOut0 = 16;               // 16-K blocks in suppP (layer0)
    const int nktOut1 = 24;

    // pack everything input-only up front (W1 at block offset 16)
    packG_k<<<(Kc * 32 * 256 * 8 * 32) / 256, 256>>>(G);
    packW_k<<<(nktOut0 * 512 + 255) / 256, 256>>>(W0, KP0, 0,  nktOut0 * 512);
    packW_k<<<(nktOut1 * 512 + 255) / 256, 256>>>(W1, KP1, 16, nktOut1 * 512);

    // ---- layer 0 ----
    {
        const int tot = (NC0 / 256) * 256 * 16 * 32;   // nt=10
        packC0_k<<<(tot + 255) / 256, 256>>>(xt, h0, tot);
    }
    gemm_fp16<0, P0><<<dim3(NC0 / BN, Nn / BM, Kc), 256, SMEM_MAIN>>>(
        GP, combP, nktG32, suppP, nktOut0,
        nullptr, nullptr, nullptr, nullptr, nullptr, nullptr);
    gemm_fp16<1, P0><<<dim3(1, ROWS / BM, 1), 256, SMEM_MAIN>>>(
        suppP, WtP, nkt0_32, nullptr, 0,
        b0, c0, out + S, nullptr, out + 3 * S, ht0);

    // ---- layer 1 ----
    {
        const int tot = (NC1 / 256) * 256 * 16 * 32;   // nt=16
        packC1_k<<<(tot + 255) / 256, 256>>>(h1, tot);
    }
    gemm_fp16<0, P1><<<dim3(NC1 / BN, Nn / BM, Kc), 256, SMEM_MAIN>>>(
        GP, combP, nktG32, suppP, nktOut1,
        nullptr, nullptr, nullptr, nullptr, nullptr, nullptr);
    gemm_fp16<1, P0><<<dim3(1, ROWS / BM, 1), 256, SMEM_MAIN>>>(
        suppP, WtP + (size_t)16 * 512, nkt1_32, nullptr, 0,
        b1, c1, out, out + 2 * S, out + 4 * S, nullptr);
}